// round 9
// baseline (speedup 1.0000x reference)
#include <cuda_runtime.h>
#include <cfloat>
#include <climits>

// Problem geometry:
//   data_in : [1, 512] f32      (d_in[0])
//   ukb_mat : [200000, 512] f32 (d_in[1])
//   pseudo  : [200000] f32      (d_in[2])
//   K       : 3
// out: [1] f32 = mean(pseudo[indices of 3 smallest L1 distances])
//
// Thread-per-row fused persistent kernel. Each thread streams its own row
// (128x LDG.128) against the query (LDS.128 broadcast from smem), so the
// hot loop has NO cross-lane shuffles and no serialized lane-0 work --
// just independent loads + FADD accumulation that ptxas can front-batch.
// Per-thread packed-u64 top-3, then warp/block/last-block-done merges.

constexpr int D        = 512;
constexpr int D4       = D / 4;           // 128 float4 per row
constexpr int KSEL     = 3;
constexpr int BLOCKS1  = 444;             // 3 CTAs/SM * 148 SMs, one wave
constexpr int THREADS1 = 256;
constexpr int WARPS1   = THREADS1 / 32;
constexpr int NCAND    = BLOCKS1 * KSEL;  // 1332 candidate keys

__device__ unsigned long long g_cand[NCAND];
__device__ unsigned int       g_counter;   // zero-init; self-reset each run

// key = (float_bits(dist) << 32) | idx. dist >= 0 so float-bit order ==
// numeric order; ties resolve to smaller index — matches jax.lax.top_k.
__device__ __forceinline__ unsigned long long mkkey(float d, unsigned idx) {
    return ((unsigned long long)__float_as_uint(d) << 32) | idx;
}

constexpr unsigned long long KEY_MAX = 0xFFFFFFFFFFFFFFFFull;

__device__ __forceinline__ void insert3(unsigned long long v, unsigned long long k[3]) {
    if (v < k[2]) {
        k[2] = v;
        if (k[2] < k[1]) { unsigned long long t = k[1]; k[1] = k[2]; k[2] = t;
            if (k[1] < k[0]) { t = k[0]; k[0] = k[1]; k[1] = t; }
        }
    }
}

__device__ __forceinline__ void warp_merge3(unsigned long long k[3]) {
    #pragma unroll
    for (int o = 16; o > 0; o >>= 1) {
        unsigned long long b0 = __shfl_xor_sync(0xFFFFFFFFu, k[0], o);
        unsigned long long b1 = __shfl_xor_sync(0xFFFFFFFFu, k[1], o);
        unsigned long long b2 = __shfl_xor_sync(0xFFFFFFFFu, k[2], o);
        insert3(b0, k); insert3(b1, k); insert3(b2, k);
    }
}

__device__ __forceinline__ float l1_4(float4 a, float4 q) {
    return fabsf(a.x - q.x) + fabsf(a.y - q.y) + fabsf(a.z - q.z) + fabsf(a.w - q.w);
}

__global__ __launch_bounds__(THREADS1, 3)
void knn_fused_kernel(const float* __restrict__ query,
                      const float* __restrict__ mat,
                      const float* __restrict__ pseudo,
                      float* __restrict__ out,
                      int N) {
    __shared__ float4 sq4[D4];
    {
        const float4* q4 = reinterpret_cast<const float4*>(query);
        for (int i = threadIdx.x; i < D4; i += THREADS1) sq4[i] = q4[i];
    }
    __syncthreads();

    const int lane   = threadIdx.x & 31;
    const int warp   = threadIdx.x >> 5;
    const int gtid   = blockIdx.x * THREADS1 + threadIdx.x;
    const int totalt = BLOCKS1 * THREADS1;

    unsigned long long k[3] = {KEY_MAX, KEY_MAX, KEY_MAX};

    // Each thread owns whole rows: consecutive lanes -> consecutive rows,
    // so a warp's LDG.128 batch covers 32 full 128B lines (all bytes used).
    for (int row = gtid; row < N; row += totalt) {
        const float4* __restrict__ r =
            reinterpret_cast<const float4*>(mat + (size_t)row * D);
        float a0 = 0.f, a1 = 0.f, a2 = 0.f, a3 = 0.f;
        #pragma unroll
        for (int c = 0; c < D4; c += 4) {
            // 4 independent streaming loads; full unroll lets ptxas
            // front-batch many iterations of loads (MLP_eff ~16).
            float4 v0 = __ldcs(r + c + 0);
            float4 v1 = __ldcs(r + c + 1);
            float4 v2 = __ldcs(r + c + 2);
            float4 v3 = __ldcs(r + c + 3);
            a0 += l1_4(v0, sq4[c + 0]);   // LDS.128 broadcast (free)
            a1 += l1_4(v1, sq4[c + 1]);
            a2 += l1_4(v2, sq4[c + 2]);
            a3 += l1_4(v3, sq4[c + 3]);
        }
        float s = (a0 + a1) + (a2 + a3);
        insert3(mkkey(s, (unsigned)row), k);
    }

    // Warp merge (every lane has candidates), then block merge.
    warp_merge3(k);

    __shared__ unsigned long long sk[WARPS1 * KSEL];
    if (lane == 0) {
        #pragma unroll
        for (int j = 0; j < KSEL; j++) sk[warp * KSEL + j] = k[j];
    }
    __syncthreads();
    if (threadIdx.x == 0) {
        unsigned long long bk[3] = {KEY_MAX, KEY_MAX, KEY_MAX};
        #pragma unroll
        for (int j = 0; j < WARPS1 * KSEL; j++) insert3(sk[j], bk);
        #pragma unroll
        for (int j = 0; j < KSEL; j++) g_cand[blockIdx.x * KSEL + j] = bk[j];
    }

    // Last-block-done global merge.
    __shared__ int s_last;
    if (threadIdx.x == 0) {
        __threadfence();
        unsigned v = atomicAdd(&g_counter, 1u);
        s_last = (v == BLOCKS1 - 1) ? 1 : 0;
    }
    __syncthreads();
    if (!s_last) return;

    unsigned long long m[3] = {KEY_MAX, KEY_MAX, KEY_MAX};
    volatile unsigned long long* cand = g_cand;
    for (int j = threadIdx.x; j < NCAND; j += THREADS1)
        insert3(cand[j], m);
    warp_merge3(m);

    __shared__ unsigned long long fk[WARPS1 * KSEL];
    if (lane == 0) {
        #pragma unroll
        for (int j = 0; j < KSEL; j++) fk[warp * KSEL + j] = m[j];
    }
    __syncthreads();
    if (threadIdx.x == 0) {
        unsigned long long bk[3] = {KEY_MAX, KEY_MAX, KEY_MAX};
        #pragma unroll
        for (int j = 0; j < WARPS1 * KSEL; j++) insert3(fk[j], bk);
        unsigned i0 = (unsigned)(bk[0] & 0xFFFFFFFFull);
        unsigned i1 = (unsigned)(bk[1] & 0xFFFFFFFFull);
        unsigned i2 = (unsigned)(bk[2] & 0xFFFFFFFFull);
        out[0] = (pseudo[i0] + pseudo[i1] + pseudo[i2]) * (1.0f / 3.0f);
        g_counter = 0;   // reset for next graph replay
    }
}

extern "C" void kernel_launch(void* const* d_in, const int* in_sizes, int n_in,
                              void* d_out, int out_size) {
    const float* query  = (const float*)d_in[0];
    const float* mat    = (const float*)d_in[1];
    const float* pseudo = (const float*)d_in[2];
    float* out = (float*)d_out;
    const int N = in_sizes[2];

    knn_fused_kernel<<<BLOCKS1, THREADS1>>>(query, mat, pseudo, out, N);
}

// round 10
// speedup vs baseline: 1.5103x; 1.5103x over previous
#include <cuda_runtime.h>
#include <cfloat>
#include <climits>

// Problem geometry:
//   data_in : [1, 512] f32      (d_in[0])
//   ukb_mat : [200000, 512] f32 (d_in[1])
//   pseudo  : [200000] f32      (d_in[2])
//   K       : 3
// out: [1] f32 = mean(pseudo[indices of 3 smallest L1 distances])
//
// Fused persistent kernel with cp.async (LDGSTS) smem staging:
// each warp owns a 3-stage x 4KB ring (one row PAIR per stage). Loads are
// issued asynchronously into smem (no register double-buffer), keeping up to
// 8KB per warp in flight while the warp computes. Coalesced layout: each lane
// writes and later reads the same smem addresses, so no barriers are needed.
// Packed dual warp reduction (6 shuffles / 2 rows), packed-u64 (dist,idx)
// top-3 keys, last-block-done global merge.

constexpr int D        = 512;
constexpr int D4       = D / 4;            // 128 float4 per row
constexpr int KSEL     = 3;
constexpr int BLOCKS1  = 296;              // 2 CTAs/SM * 148 SMs
constexpr int THREADS1 = 256;              // 8 warps
constexpr int WARPS1   = THREADS1 / 32;
constexpr int STAGES   = 3;                // pairs in flight per warp
constexpr int STAGE_F4 = 2 * D4;           // 256 float4 per pair stage (4KB)
constexpr int NCAND    = BLOCKS1 * KSEL;

// dynamic smem: [0, D4) = query, then WARPS1*STAGES stages of STAGE_F4 float4
constexpr int SMEM_F4    = D4 + WARPS1 * STAGES * STAGE_F4;
constexpr int SMEM_BYTES = SMEM_F4 * 16;   // 100,352 B per CTA

__device__ unsigned long long g_cand[NCAND];
__device__ unsigned int       g_counter;   // zero-init; self-reset each run

__device__ __forceinline__ unsigned long long mkkey(float d, unsigned idx) {
    return ((unsigned long long)__float_as_uint(d) << 32) | idx;
}
constexpr unsigned long long KEY_MAX = 0xFFFFFFFFFFFFFFFFull;

__device__ __forceinline__ void insert3(unsigned long long v, unsigned long long k[3]) {
    if (v < k[2]) {
        k[2] = v;
        if (k[2] < k[1]) { unsigned long long t = k[1]; k[1] = k[2]; k[2] = t;
            if (k[1] < k[0]) { t = k[0]; k[0] = k[1]; k[1] = t; }
        }
    }
}

__device__ __forceinline__ void warp_merge3(unsigned long long k[3]) {
    #pragma unroll
    for (int o = 16; o > 0; o >>= 1) {
        unsigned long long b0 = __shfl_xor_sync(0xFFFFFFFFu, k[0], o);
        unsigned long long b1 = __shfl_xor_sync(0xFFFFFFFFu, k[1], o);
        unsigned long long b2 = __shfl_xor_sync(0xFFFFFFFFu, k[2], o);
        insert3(b0, k); insert3(b1, k); insert3(b2, k);
    }
}

__device__ __forceinline__ float l1_4(float4 a, float4 q) {
    return fabsf(a.x - q.x) + fabsf(a.y - q.y) + fabsf(a.z - q.z) + fabsf(a.w - q.w);
}

__device__ __forceinline__ void cpasync16(float4* dst, const float4* src) {
    unsigned s = (unsigned)__cvta_generic_to_shared(dst);
    asm volatile("cp.async.cg.shared.global [%0], [%1], 16;" :: "r"(s), "l"(src));
}
#define CP_COMMIT()  asm volatile("cp.async.commit_group;" ::: "memory")
#define CP_WAIT(n)   asm volatile("cp.async.wait_group %0;" :: "n"(n) : "memory")

// Issue one pair (rows 2p, 2p+1) into a stage: 8 x 16B per lane, coalesced.
__device__ __forceinline__ void issue_pair(float4* stage, const float4* mat4,
                                           int pair, int lane) {
    const float4* ra = mat4 + (size_t)(2 * pair)     * D4;
    const float4* rb = mat4 + (size_t)(2 * pair + 1) * D4;
    #pragma unroll
    for (int i = 0; i < 4; i++)
        cpasync16(stage + i * 32 + lane,       ra + i * 32 + lane);
    #pragma unroll
    for (int i = 0; i < 4; i++)
        cpasync16(stage + D4 + i * 32 + lane,  rb + i * 32 + lane);
}

__global__ __launch_bounds__(THREADS1, 2)
void knn_fused_kernel(const float* __restrict__ query,
                      const float* __restrict__ mat,
                      const float* __restrict__ pseudo,
                      float* __restrict__ out,
                      int N) {
    extern __shared__ float4 smem[];
    float4* sq4 = smem;
    {
        const float4* q4 = reinterpret_cast<const float4*>(query);
        for (int i = threadIdx.x; i < D4; i += THREADS1) sq4[i] = q4[i];
    }
    __syncthreads();

    const int lane  = threadIdx.x & 31;
    const int warp  = threadIdx.x >> 5;
    const int gwarp = blockIdx.x * WARPS1 + warp;
    const int nwarp = BLOCKS1 * WARPS1;
    const float4* mat4 = reinterpret_cast<const float4*>(mat);

    float4* ring = smem + D4 + warp * (STAGES * STAGE_F4);

    const float4 q0 = sq4[lane +  0];
    const float4 q1 = sq4[lane + 32];
    const float4 q2 = sq4[lane + 64];
    const float4 q3 = sq4[lane + 96];

    unsigned long long k[3] = {KEY_MAX, KEY_MAX, KEY_MAX};

    const int npairs = N >> 1;

    // Prologue: fill the ring (commit a group per stage even if empty so the
    // wait_group accounting stays uniform).
    int fill = gwarp;
    #pragma unroll
    for (int s = 0; s < STAGES; s++) {
        if (fill < npairs) issue_pair(ring + s * STAGE_F4, mat4, fill, lane);
        CP_COMMIT();
        if (fill < npairs) fill += nwarp;
    }

    int slot = 0;
    for (int p = gwarp; p < npairs; p += nwarp) {
        CP_WAIT(STAGES - 1);                 // oldest stage complete
        const float4* st = ring + slot * STAGE_F4;
        // Each lane reads exactly the addresses it wrote -> no barrier needed.
        float4 a0 = st[lane +  0];
        float4 a1 = st[lane + 32];
        float4 a2 = st[lane + 64];
        float4 a3 = st[lane + 96];
        float4 b0 = st[D4 + lane +  0];
        float4 b1 = st[D4 + lane + 32];
        float4 b2 = st[D4 + lane + 64];
        float4 b3 = st[D4 + lane + 96];
        float sa = l1_4(a0, q0) + l1_4(a1, q1) + l1_4(a2, q2) + l1_4(a3, q3);
        float sb = l1_4(b0, q0) + l1_4(b1, q1) + l1_4(b2, q2) + l1_4(b3, q3);

        // Slot fully consumed (values folded into sa/sb) -> refill it now so
        // the new requests are in flight during the serial shuffle chain.
        if (fill < npairs) { issue_pair(ring + slot * STAGE_F4, mat4, fill, lane); fill += nwarp; }
        CP_COMMIT();

        // Packed dual reduction: fold each row to 16 partials, pack row a in
        // the lower half-warp and row b in the upper, 4-step butterfly.
        float va = sa + __shfl_xor_sync(0xFFFFFFFFu, sa, 16);
        float vb = sb + __shfl_xor_sync(0xFFFFFFFFu, sb, 16);
        float v  = (lane < 16) ? va : vb;
        #pragma unroll
        for (int o = 8; o > 0; o >>= 1)
            v += __shfl_xor_sync(0xFFFFFFFFu, v, o);
        int row = 2 * p;
        if (lane == 0)       insert3(mkkey(v, (unsigned)row),       k);
        else if (lane == 16) insert3(mkkey(v, (unsigned)(row + 1)), k);

        slot = (slot + 1 < STAGES) ? slot + 1 : 0;
    }
    CP_WAIT(0);   // drain

    // Odd-N tail: one leftover row, handled by warp 0 with plain loads.
    if ((N & 1) && gwarp == 0) {
        const float4* ra = mat4 + (size_t)(N - 1) * D4;
        float s = l1_4(__ldcs(ra + lane +  0), q0) + l1_4(__ldcs(ra + lane + 32), q1)
                + l1_4(__ldcs(ra + lane + 64), q2) + l1_4(__ldcs(ra + lane + 96), q3);
        #pragma unroll
        for (int o = 16; o > 0; o >>= 1)
            s += __shfl_xor_sync(0xFFFFFFFFu, s, o);
        if (lane == 0) insert3(mkkey(s, (unsigned)(N - 1)), k);
    }

    // Merge lanes 0/16, then block merge.
    warp_merge3(k);

    __shared__ unsigned long long sk[WARPS1 * KSEL];
    if (lane == 0) {
        #pragma unroll
        for (int j = 0; j < KSEL; j++) sk[warp * KSEL + j] = k[j];
    }
    __syncthreads();
    if (threadIdx.x == 0) {
        unsigned long long bk[3] = {KEY_MAX, KEY_MAX, KEY_MAX};
        #pragma unroll
        for (int j = 0; j < WARPS1 * KSEL; j++) insert3(sk[j], bk);
        #pragma unroll
        for (int j = 0; j < KSEL; j++) g_cand[blockIdx.x * KSEL + j] = bk[j];
    }

    // Last-block-done global merge.
    __shared__ int s_last;
    if (threadIdx.x == 0) {
        __threadfence();
        unsigned v = atomicAdd(&g_counter, 1u);
        s_last = (v == BLOCKS1 - 1) ? 1 : 0;
    }
    __syncthreads();
    if (!s_last) return;

    unsigned long long m[3] = {KEY_MAX, KEY_MAX, KEY_MAX};
    volatile unsigned long long* cand = g_cand;
    for (int j = threadIdx.x; j < NCAND; j += THREADS1)
        insert3(cand[j], m);
    warp_merge3(m);

    __shared__ unsigned long long fk[WARPS1 * KSEL];
    if (lane == 0) {
        #pragma unroll
        for (int j = 0; j < KSEL; j++) fk[warp * KSEL + j] = m[j];
    }
    __syncthreads();
    if (threadIdx.x == 0) {
        unsigned long long bk[3] = {KEY_MAX, KEY_MAX, KEY_MAX};
        #pragma unroll
        for (int j = 0; j < WARPS1 * KSEL; j++) insert3(fk[j], bk);
        unsigned i0 = (unsigned)(bk[0] & 0xFFFFFFFFull);
        unsigned i1 = (unsigned)(bk[1] & 0xFFFFFFFFull);
        unsigned i2 = (unsigned)(bk[2] & 0xFFFFFFFFull);
        out[0] = (pseudo[i0] + pseudo[i1] + pseudo[i2]) * (1.0f / 3.0f);
        g_counter = 0;   // reset for next graph replay
    }
}

extern "C" void kernel_launch(void* const* d_in, const int* in_sizes, int n_in,
                              void* d_out, int out_size) {
    const float* query  = (const float*)d_in[0];
    const float* mat    = (const float*)d_in[1];
    const float* pseudo = (const float*)d_in[2];
    float* out = (float*)d_out;
    const int N = in_sizes[2];

    static bool attr_set = false;
    if (!attr_set) {
        cudaFuncSetAttribute(knn_fused_kernel,
                             cudaFuncAttributeMaxDynamicSharedMemorySize, SMEM_BYTES);
        attr_set = true;
    }
    knn_fused_kernel<<<BLOCKS1, THREADS1, SMEM_BYTES>>>(query, mat, pseudo, out, N);
}